// round 8
// baseline (speedup 1.0000x reference)
#include <cuda_runtime.h>
#include <cstdint>

// FPS: B=8, N=65536, select 1024. One cluster per batch.
// Preferred: 16 CTAs x 512 thr (4 warps/SMSP -> half issue pressure).
// Fallback:   8 CTAs x 1024 thr (round-4 proven).
// st.async+mbarrier key exchange; consumer reduce = u64 register tree.

#define FPS_B  8
#define FPS_N  65536
#define FPS_NP 1024

__device__ __forceinline__ uint64_t pack2(float a, float b) {
    uint64_t r; asm("mov.b64 %0, {%1, %2};" : "=l"(r) : "f"(a), "f"(b)); return r;
}
__device__ __forceinline__ void unpack2(uint64_t v, float& a, float& b) {
    asm("mov.b64 {%0, %1}, %2;" : "=f"(a), "=f"(b) : "l"(v));
}
__device__ __forceinline__ uint64_t add2(uint64_t a, uint64_t b) {
    uint64_t r; asm("add.rn.f32x2 %0, %1, %2;" : "=l"(r) : "l"(a), "l"(b)); return r;
}
__device__ __forceinline__ uint64_t mul2(uint64_t a, uint64_t b) {
    uint64_t r; asm("mul.rn.f32x2 %0, %1, %2;" : "=l"(r) : "l"(a), "l"(b)); return r;
}
__device__ __forceinline__ uint32_t ctarank() {
    uint32_t r; asm("mov.u32 %0, %%cluster_ctarank;" : "=r"(r)); return r;
}
__device__ __forceinline__ uint32_t smem_u32(const void* p) {
    uint32_t a;
    asm("{ .reg .u64 t; cvta.to.shared.u64 t, %1; cvt.u32.u64 %0, t; }" : "=r"(a) : "l"(p));
    return a;
}
__device__ __forceinline__ uint32_t redux_max_u32(uint32_t v) {
    uint32_t r; asm("redux.sync.max.u32 %0, %1, 0xFFFFFFFF;" : "=r"(r) : "r"(v)); return r;
}
__device__ __forceinline__ uint32_t redux_min_u32(uint32_t v) {
    uint32_t r; asm("redux.sync.min.u32 %0, %1, 0xFFFFFFFF;" : "=r"(r) : "r"(v)); return r;
}
__device__ __forceinline__ void mbar_init(uint32_t mbar, uint32_t cnt) {
    asm volatile("mbarrier.init.shared.b64 [%0], %1;" :: "r"(mbar), "r"(cnt) : "memory");
}
__device__ __forceinline__ void mbar_expect_tx(uint32_t mbar, uint32_t bytes) {
    asm volatile("mbarrier.arrive.expect_tx.shared.b64 _, [%0], %1;"
                 :: "r"(mbar), "r"(bytes) : "memory");
}
__device__ __forceinline__ void mbar_wait(uint32_t mbar, uint32_t parity) {
    asm volatile(
        "{\n\t"
        ".reg .pred P;\n\t"
        "WL_%=:\n\t"
        "mbarrier.try_wait.parity.acquire.cluster.shared::cta.b64 P, [%0], %1, 0x989680;\n\t"
        "@P bra.uni WD_%=;\n\t"
        "bra.uni WL_%=;\n\t"
        "WD_%=:\n\t"
        "}"
        :: "r"(mbar), "r"(parity) : "memory");
}
__device__ __forceinline__ uint32_t mapa32(uint32_t laddr, uint32_t rank) {
    uint32_t r;
    asm("mapa.shared::cluster.u32 %0, %1, %2;" : "=r"(r) : "r"(laddr), "r"(rank));
    return r;
}
__device__ __forceinline__ void st_async_u64(uint32_t raddr, uint64_t v, uint32_t rmbar) {
    asm volatile("st.async.shared::cluster.mbarrier::complete_tx::bytes.b64 [%0], %1, [%2];"
                 :: "r"(raddr), "l"(v), "r"(rmbar) : "memory");
}
__device__ __forceinline__ uint64_t u64max(uint64_t a, uint64_t b) { return a > b ? a : b; }

template<int CL, int T>
__global__ void __launch_bounds__(T, 1)
fps_kernel(const float* __restrict__ pts, float* __restrict__ out) {
    constexpr int PT    = FPS_N / (CL * T);    // points per thread (8 for both shapes)
    constexpr int NF4   = PT / 4;
    constexpr int NPAIR = PT / 2;
    constexpr int NW    = T / 32;
    constexpr uint32_t XBYTES = 8u * CL;

    const int b      = blockIdx.x / CL;
    const uint32_t k = ctarank();
    const int tid    = threadIdx.x;
    const int lane   = tid & 31;
    const int wid    = tid >> 5;

    const float* __restrict__ xb = pts + (size_t)b * 3 * FPS_N;
    const float4* __restrict__ x4 = (const float4*)(xb);
    const float4* __restrict__ y4 = (const float4*)(xb + FPS_N);
    const float4* __restrict__ z4 = (const float4*)(xb + 2 * FPS_N);

    uint64_t xp[NPAIR], yp[NPAIR], zp[NPAIR];
    float dist[PT];
    int pbase[NF4];

#pragma unroll
    for (int j = 0; j < NF4; j++) {
        int f = (int)k * (FPS_N / 4 / CL) + tid + T * j;
        pbase[j] = 4 * f;
        float4 vx = x4[f], vy = y4[f], vz = z4[f];
        xp[2*j+0] = pack2(vx.x, vx.y);  xp[2*j+1] = pack2(vx.z, vx.w);
        yp[2*j+0] = pack2(vy.x, vy.y);  yp[2*j+1] = pack2(vy.z, vy.w);
        zp[2*j+0] = pack2(vz.x, vz.y);  zp[2*j+1] = pack2(vz.z, vz.w);
    }
#pragma unroll
    for (int p = 0; p < PT; p++) dist[p] = 1e10f;

    __shared__ uint64_t s_wkey[NW];                        // (d<<32)|~i per warp
    __shared__ alignas(16) unsigned long long s_key[2][CL];
    __shared__ alignas(8)  uint64_t s_mbar[2];
    __shared__ uint32_t s_hist[FPS_NP];

    const uint32_t mb0 = smem_u32(&s_mbar[0]);
    const uint32_t mb1 = smem_u32(&s_mbar[1]);

    uint32_t r_slot0 = 0, r_slot1 = 0, r_mb0 = 0, r_mb1 = 0;
    if (wid == 0 && lane < CL) {
        r_slot0 = mapa32(smem_u32(&s_key[0][k]), (uint32_t)lane);
        r_slot1 = mapa32(smem_u32(&s_key[1][k]), (uint32_t)lane);
        r_mb0   = mapa32(mb0, (uint32_t)lane);
        r_mb1   = mapa32(mb1, (uint32_t)lane);
    }

    if (tid == 0) {
        mbar_init(mb0, 1);
        mbar_init(mb1, 1);
        mbar_expect_tx(mb0, XBYTES);
        mbar_expect_tx(mb1, XBYTES);
        s_hist[0] = 0;
    }
    __syncthreads();
    asm volatile("barrier.cluster.arrive.aligned;" ::: "memory");
    asm volatile("barrier.cluster.wait.aligned;"   ::: "memory");

    float px = __ldg(&xb[0]);
    float py = __ldg(&xb[FPS_N]);
    float pz = __ldg(&xb[2 * FPS_N]);

    for (int it = 1; it < FPS_NP; it++) {
        const int u        = it - 1;
        const int buf      = u & 1;
        const uint32_t par = (u >> 1) & 1;
        const uint32_t mb     = buf ? mb1 : mb0;
        const uint32_t r_slot = buf ? r_slot1 : r_slot0;
        const uint32_t r_mb   = buf ? r_mb1 : r_mb0;

        uint64_t npx = pack2(-px, -px);
        uint64_t npy = pack2(-py, -py);
        uint64_t npz = pack2(-pz, -pz);

        // proven hot loop: packed distance + SEL-chain first-index argmax
        float bestd  = -1.0f;
        int   bestid = 0;
#pragma unroll
        for (int q = 0; q < NPAIR; q++) {
            uint64_t dx = add2(xp[q], npx);        // add(x,-p) bitwise == sub(x,p)
            uint64_t dy = add2(yp[q], npy);
            uint64_t dz = add2(zp[q], npz);
            // XLA order: (dx^2 + dy^2) + dz^2, separate .rn rounding
            uint64_t s = add2(add2(mul2(dx, dx), mul2(dy, dy)), mul2(dz, dz));
            float d0, d1; unpack2(s, d0, d1);
            const int p   = 2 * q;
            const int idx = pbase[q >> 1] + 2 * (q & 1);
            float n0 = fminf(dist[p], d0);     dist[p]     = n0;
            if (n0 > bestd) { bestd = n0; bestid = idx; }      // strict >: first idx wins
            float n1 = fminf(dist[p + 1], d1); dist[p + 1] = n1;
            if (n1 > bestd) { bestd = n1; bestid = idx + 1; }
        }

        // warp argmax (dists >= 0: u32 order == float order); first-index tie-break
        uint32_t db   = __float_as_uint(bestd);
        uint32_t wmax = redux_max_u32(db);
        uint32_t cand = (db == wmax) ? (uint32_t)bestid : 0xFFFFFFFFu;
        uint32_t wmin = redux_min_u32(cand);
        if (db == wmax && (uint32_t)bestid == wmin)            // unique owner lane
            s_wkey[wid] = ((uint64_t)wmax << 32) | (uint64_t)(~wmin);

        if (wid == 0) {
            asm volatile("bar.sync 1, %0;" :: "r"(T) : "memory");
            uint64_t wkey = (lane < NW) ? s_wkey[lane] : 0ull;
            uint32_t d  = (uint32_t)(wkey >> 32);
            uint32_t ni = (uint32_t)wkey;
            uint32_t m   = redux_max_u32(d);
            uint32_t nim = redux_max_u32((d == m) ? ni : 0u);  // max ~i == min i
            if (lane < CL) {
                uint64_t key = ((uint64_t)m << 32) | (uint64_t)nim;
                st_async_u64(r_slot, key, r_mb);
            }
        } else {
            asm volatile("bar.arrive 1, %0;" :: "r"(T) : "memory");
        }

        mbar_wait(mb, par);

        // consumer reduce: u64 register tree (broadcast LDS, fixed-lat ALU)
        const ulonglong2* kp = (const ulonglong2*)&s_key[buf][0];
        unsigned long long m[CL / 2];
#pragma unroll
        for (int i = 0; i < CL / 2; i++) {
            ulonglong2 a = kp[i];
            m[i] = u64max(a.x, a.y);
        }
#pragma unroll
        for (int s = CL / 4; s >= 1; s >>= 1)
#pragma unroll
            for (int i = 0; i < s; i++) m[i] = u64max(m[i], m[i + s]);
        const unsigned long long w = m[0];
        const int widx = (int)(~(uint32_t)w);

        if (tid == 0) {
            s_hist[it] = (uint32_t)widx;
            mbar_expect_tx(mb, XBYTES);            // next phase of this buffer
        }

        px = __ldcg(&xb[widx]);
        py = __ldcg(&xb[FPS_N + widx]);
        pz = __ldcg(&xb[2 * FPS_N + widx]);
    }

    // final gather: rank-0 CTA writes (3, 1024) for its batch
    __syncthreads();
    if (k == 0) {
        for (int i = tid; i < 3 * FPS_NP; i += T) {
            int ip = i & (FPS_NP - 1);
            int c  = i >> 10;
            uint32_t idx = s_hist[ip];
            out[((size_t)b * 3 + c) * FPS_NP + ip] = xb[(size_t)c * FPS_N + idx];
        }
    }
}

extern "C" void kernel_launch(void* const* d_in, const int* in_sizes, int n_in,
                              void* d_out, int out_size) {
    const float* pts = (const float*)d_in[0];
    float* out = (float*)d_out;

    // ---- probe 16-CTA x 512-thread non-portable clusters (host-side, capture-safe)
    bool ok16 = false;
    if (cudaFuncSetAttribute(fps_kernel<16, 512>,
                             cudaFuncAttributeNonPortableClusterSizeAllowed, 1) == cudaSuccess) {
        // 1) clean attr-free config for MaxPotentialClusterSize
        cudaLaunchConfig_t q = {};
        q.gridDim  = dim3(FPS_B * 16, 1, 1);
        q.blockDim = dim3(512, 1, 1);
        q.attrs = nullptr;
        q.numAttrs = 0;
        int mcs = 0;
        if (cudaOccupancyMaxPotentialClusterSize(&mcs, fps_kernel<16, 512>, &q) == cudaSuccess &&
            mcs >= 16) {
            // 2) all 8 clusters must be co-resident (waves would serialize batches)
            cudaLaunchAttribute a2[1];
            a2[0].id = cudaLaunchAttributeClusterDimension;
            a2[0].val.clusterDim = {16, 1, 1};
            q.attrs = a2;
            q.numAttrs = 1;
            int nc = 0;
            if (cudaOccupancyMaxActiveClusters(&nc, fps_kernel<16, 512>, &q) == cudaSuccess &&
                nc >= FPS_B)
                ok16 = true;
        }
    }
    (void)cudaGetLastError();

    cudaLaunchConfig_t cfg = {};
    cudaLaunchAttribute at[1];
    at[0].id = cudaLaunchAttributeClusterDimension;
    cfg.attrs = at;
    cfg.numAttrs = 1;
    cfg.stream = 0;

    if (ok16) {
        cfg.gridDim  = dim3(FPS_B * 16, 1, 1);
        cfg.blockDim = dim3(512, 1, 1);
        at[0].val.clusterDim = {16, 1, 1};
        cudaLaunchKernelEx(&cfg, fps_kernel<16, 512>, pts, out);
    } else {
        cfg.gridDim  = dim3(FPS_B * 8, 1, 1);
        cfg.blockDim = dim3(1024, 1, 1);
        at[0].val.clusterDim = {8, 1, 1};
        cudaLaunchKernelEx(&cfg, fps_kernel<8, 1024>, pts, out);
    }
}

// round 9
// speedup vs baseline: 1.2229x; 1.2229x over previous
#include <cuda_runtime.h>
#include <cstdint>

// FPS: B=8, N=65536, select 1024. One cluster per batch.
// Round-4 proven structure: st.async+mbarrier key exchange, redux reduces.
// Probe 16x1024 clusters via MaxActiveClusters only; fallback 8x1024.

#define FPS_B  8
#define FPS_N  65536
#define FPS_NP 1024

__device__ __forceinline__ uint64_t pack2(float a, float b) {
    uint64_t r; asm("mov.b64 %0, {%1, %2};" : "=l"(r) : "f"(a), "f"(b)); return r;
}
__device__ __forceinline__ void unpack2(uint64_t v, float& a, float& b) {
    asm("mov.b64 {%0, %1}, %2;" : "=f"(a), "=f"(b) : "l"(v));
}
__device__ __forceinline__ uint64_t add2(uint64_t a, uint64_t b) {
    uint64_t r; asm("add.rn.f32x2 %0, %1, %2;" : "=l"(r) : "l"(a), "l"(b)); return r;
}
__device__ __forceinline__ uint64_t mul2(uint64_t a, uint64_t b) {
    uint64_t r; asm("mul.rn.f32x2 %0, %1, %2;" : "=l"(r) : "l"(a), "l"(b)); return r;
}
__device__ __forceinline__ uint32_t ctarank() {
    uint32_t r; asm("mov.u32 %0, %%cluster_ctarank;" : "=r"(r)); return r;
}
__device__ __forceinline__ uint32_t smem_u32(const void* p) {
    uint32_t a;
    asm("{ .reg .u64 t; cvta.to.shared.u64 t, %1; cvt.u32.u64 %0, t; }" : "=r"(a) : "l"(p));
    return a;
}
__device__ __forceinline__ uint32_t redux_max_u32(uint32_t v) {
    uint32_t r; asm("redux.sync.max.u32 %0, %1, 0xFFFFFFFF;" : "=r"(r) : "r"(v)); return r;
}
__device__ __forceinline__ uint32_t redux_min_u32(uint32_t v) {
    uint32_t r; asm("redux.sync.min.u32 %0, %1, 0xFFFFFFFF;" : "=r"(r) : "r"(v)); return r;
}
__device__ __forceinline__ void mbar_init(uint32_t mbar, uint32_t cnt) {
    asm volatile("mbarrier.init.shared.b64 [%0], %1;" :: "r"(mbar), "r"(cnt) : "memory");
}
__device__ __forceinline__ void mbar_expect_tx(uint32_t mbar, uint32_t bytes) {
    asm volatile("mbarrier.arrive.expect_tx.shared.b64 _, [%0], %1;"
                 :: "r"(mbar), "r"(bytes) : "memory");
}
__device__ __forceinline__ void mbar_wait(uint32_t mbar, uint32_t parity) {
    asm volatile(
        "{\n\t"
        ".reg .pred P;\n\t"
        "WL_%=:\n\t"
        "mbarrier.try_wait.parity.acquire.cluster.shared::cta.b64 P, [%0], %1, 0x989680;\n\t"
        "@P bra.uni WD_%=;\n\t"
        "bra.uni WL_%=;\n\t"
        "WD_%=:\n\t"
        "}"
        :: "r"(mbar), "r"(parity) : "memory");
}
__device__ __forceinline__ uint32_t mapa32(uint32_t laddr, uint32_t rank) {
    uint32_t r;
    asm("mapa.shared::cluster.u32 %0, %1, %2;" : "=r"(r) : "r"(laddr), "r"(rank));
    return r;
}
__device__ __forceinline__ void st_async_u64(uint32_t raddr, uint64_t v, uint32_t rmbar) {
    asm volatile("st.async.shared::cluster.mbarrier::complete_tx::bytes.b64 [%0], %1, [%2];"
                 :: "r"(raddr), "l"(v), "r"(rmbar) : "memory");
}
__device__ __forceinline__ void lds_v2(uint32_t addr, uint32_t& a, uint32_t& b) {
    asm volatile("ld.shared.v2.u32 {%0, %1}, [%2];" : "=r"(a), "=r"(b) : "r"(addr));
}

template<int CL, int T>
__global__ void __launch_bounds__(T, 1)
fps_kernel(const float* __restrict__ pts, float* __restrict__ out) {
    constexpr int PT    = FPS_N / (CL * T);    // 8 (CL8/T1024) or 4 (CL16/T1024)
    constexpr int NF4   = PT / 4;
    constexpr int NPAIR = PT / 2;
    constexpr int NW    = T / 32;
    constexpr uint32_t XBYTES = 8u * CL;

    const int b      = blockIdx.x / CL;
    const uint32_t k = ctarank();
    const int tid    = threadIdx.x;
    const int lane   = tid & 31;
    const int wid    = tid >> 5;

    const float* __restrict__ xb = pts + (size_t)b * 3 * FPS_N;
    const float4* __restrict__ x4 = (const float4*)(xb);
    const float4* __restrict__ y4 = (const float4*)(xb + FPS_N);
    const float4* __restrict__ z4 = (const float4*)(xb + 2 * FPS_N);

    uint64_t xp[NPAIR], yp[NPAIR], zp[NPAIR];
    float dist[PT];
    int pbase[NF4];

#pragma unroll
    for (int j = 0; j < NF4; j++) {
        int f = (int)k * (FPS_N / 4 / CL) + tid + T * j;
        pbase[j] = 4 * f;
        float4 vx = x4[f], vy = y4[f], vz = z4[f];
        xp[2*j+0] = pack2(vx.x, vx.y);  xp[2*j+1] = pack2(vx.z, vx.w);
        yp[2*j+0] = pack2(vy.x, vy.y);  yp[2*j+1] = pack2(vy.z, vy.w);
        zp[2*j+0] = pack2(vz.x, vz.y);  zp[2*j+1] = pack2(vz.z, vz.w);
    }
#pragma unroll
    for (int p = 0; p < PT; p++) dist[p] = 1e10f;

    __shared__ uint64_t s_wkey[NW];                       // (d<<32)|~i per warp
    __shared__ alignas(16) unsigned long long s_key[2][CL];  // exchange: lo=d, hi=~i
    __shared__ alignas(8)  uint64_t s_mbar[2];
    __shared__ uint32_t s_hist[FPS_NP];

    const uint32_t mb0 = smem_u32(&s_mbar[0]);
    const uint32_t mb1 = smem_u32(&s_mbar[1]);
    const uint32_t pair0 = smem_u32(&s_key[0][0]);
    const uint32_t pair1 = smem_u32(&s_key[1][0]);

    uint32_t r_slot0 = 0, r_slot1 = 0, r_mb0 = 0, r_mb1 = 0;
    if (wid == 0 && lane < CL) {
        r_slot0 = mapa32(pair0 + 8u * k, (uint32_t)lane);
        r_slot1 = mapa32(pair1 + 8u * k, (uint32_t)lane);
        r_mb0   = mapa32(mb0, (uint32_t)lane);
        r_mb1   = mapa32(mb1, (uint32_t)lane);
    }

    if (tid == 0) {
        mbar_init(mb0, 1);
        mbar_init(mb1, 1);
        mbar_expect_tx(mb0, XBYTES);
        mbar_expect_tx(mb1, XBYTES);
        s_hist[0] = 0;
    }
    __syncthreads();
    asm volatile("barrier.cluster.arrive.aligned;" ::: "memory");
    asm volatile("barrier.cluster.wait.aligned;"   ::: "memory");

    float px = __ldg(&xb[0]);
    float py = __ldg(&xb[FPS_N]);
    float pz = __ldg(&xb[2 * FPS_N]);

    for (int it = 1; it < FPS_NP; it++) {
        const int u        = it - 1;
        const int buf      = u & 1;
        const uint32_t par = (u >> 1) & 1;
        const uint32_t mb     = buf ? mb1 : mb0;
        const uint32_t pbuf   = buf ? pair1 : pair0;
        const uint32_t r_slot = buf ? r_slot1 : r_slot0;
        const uint32_t r_mb   = buf ? r_mb1 : r_mb0;

        uint64_t npx = pack2(-px, -px);
        uint64_t npy = pack2(-py, -py);
        uint64_t npz = pack2(-pz, -pz);

        // proven hot loop: packed distance + SEL-chain first-index argmax
        float bestd  = -1.0f;
        int   bestid = 0;
#pragma unroll
        for (int q = 0; q < NPAIR; q++) {
            uint64_t dx = add2(xp[q], npx);        // add(x,-p) bitwise == sub(x,p)
            uint64_t dy = add2(yp[q], npy);
            uint64_t dz = add2(zp[q], npz);
            // XLA order: (dx^2 + dy^2) + dz^2, separate .rn rounding
            uint64_t s = add2(add2(mul2(dx, dx), mul2(dy, dy)), mul2(dz, dz));
            float d0, d1; unpack2(s, d0, d1);
            const int p   = 2 * q;
            const int idx = pbase[q >> 1] + 2 * (q & 1);
            float n0 = fminf(dist[p], d0);     dist[p]     = n0;
            if (n0 > bestd) { bestd = n0; bestid = idx; }      // strict >: first idx wins
            float n1 = fminf(dist[p + 1], d1); dist[p + 1] = n1;
            if (n1 > bestd) { bestd = n1; bestid = idx + 1; }
        }

        // warp argmax (dists >= 0: u32 order == float order); first-index tie-break
        uint32_t db   = __float_as_uint(bestd);
        uint32_t wmax = redux_max_u32(db);
        uint32_t cand = (db == wmax) ? (uint32_t)bestid : 0xFFFFFFFFu;
        uint32_t wmin = redux_min_u32(cand);
        if (db == wmax && (uint32_t)bestid == wmin)            // unique owner lane
            s_wkey[wid] = ((uint64_t)wmax << 32) | (uint64_t)(~wmin);

        if (wid == 0) {
            asm volatile("bar.sync 1, %0;" :: "r"(T) : "memory");
            uint64_t wkey = s_wkey[lane & (NW - 1)];           // NW==32 -> all lanes valid
            uint32_t d  = (uint32_t)(wkey >> 32);
            uint32_t ni = (uint32_t)wkey;
            uint32_t m   = redux_max_u32(d);
            uint32_t nim = redux_max_u32((d == m) ? ni : 0u);  // max ~i == min i
            if (lane < CL) {
                uint64_t msg = ((uint64_t)nim << 32) | (uint64_t)m;   // lo=d, hi=~i
                st_async_u64(r_slot, msg, r_mb);
            }
        } else {
            asm volatile("bar.arrive 1, %0;" :: "r"(T) : "memory");
        }

        mbar_wait(mb, par);

        // per-warp reduce of CL exchanged candidates: 1 LDS.v2 + 2 redux
        uint32_t d = 0, ni = 0;
        if (lane < CL) lds_v2(pbuf + 8u * (uint32_t)lane, d, ni);
        uint32_t dm  = redux_max_u32(d);
        uint32_t nim = redux_max_u32((lane < CL && d == dm) ? ni : 0u);
        const int widx = (int)(~nim);

        // pivot fetch first (longest-latency op on the serial chain)
        px = __ldcg(&xb[widx]);
        py = __ldcg(&xb[FPS_N + widx]);
        pz = __ldcg(&xb[2 * FPS_N + widx]);

        if (tid == 0) {
            s_hist[it] = (uint32_t)widx;
            mbar_expect_tx(mb, XBYTES);            // next phase of this buffer
        }
    }

    // final gather: rank-0 CTA writes (3, 1024) for its batch
    __syncthreads();
    if (k == 0) {
        for (int i = tid; i < 3 * FPS_NP; i += T) {
            int ip = i & (FPS_NP - 1);
            int c  = i >> 10;
            uint32_t idx = s_hist[ip];
            out[((size_t)b * 3 + c) * FPS_NP + ip] = xb[(size_t)c * FPS_N + idx];
        }
    }
}

extern "C" void kernel_launch(void* const* d_in, const int* in_sizes, int n_in,
                              void* d_out, int out_size) {
    const float* pts = (const float*)d_in[0];
    float* out = (float*)d_out;

    // probe 16x1024 non-portable clusters: single authoritative query
    bool ok16 = false;
    if (cudaFuncSetAttribute(fps_kernel<16, 1024>,
                             cudaFuncAttributeNonPortableClusterSizeAllowed, 1) == cudaSuccess) {
        cudaLaunchConfig_t q = {};
        q.gridDim  = dim3(FPS_B * 16, 1, 1);
        q.blockDim = dim3(1024, 1, 1);
        cudaLaunchAttribute qa[1];
        qa[0].id = cudaLaunchAttributeClusterDimension;
        qa[0].val.clusterDim = {16, 1, 1};
        q.attrs = qa;
        q.numAttrs = 1;
        int nc = 0;
        if (cudaOccupancyMaxActiveClusters(&nc, fps_kernel<16, 1024>, &q) == cudaSuccess &&
            nc >= FPS_B)
            ok16 = true;
    }
    (void)cudaGetLastError();

    cudaLaunchConfig_t cfg = {};
    cudaLaunchAttribute at[1];
    at[0].id = cudaLaunchAttributeClusterDimension;
    cfg.attrs = at;
    cfg.numAttrs = 1;
    cfg.stream = 0;

    if (ok16) {
        cfg.gridDim  = dim3(FPS_B * 16, 1, 1);
        cfg.blockDim = dim3(1024, 1, 1);
        at[0].val.clusterDim = {16, 1, 1};
        cudaLaunchKernelEx(&cfg, fps_kernel<16, 1024>, pts, out);
    } else {
        cfg.gridDim  = dim3(FPS_B * 8, 1, 1);
        cfg.blockDim = dim3(1024, 1, 1);
        at[0].val.clusterDim = {8, 1, 1};
        cudaLaunchKernelEx(&cfg, fps_kernel<8, 1024>, pts, out);
    }
}

// round 10
// speedup vs baseline: 1.2556x; 1.0267x over previous
#include <cuda_runtime.h>
#include <cstdint>

// FPS: B=8, N=65536, select 1024. 8-CTA cluster per batch.
// Exchange: plain st.shared::cluster with tag-embedded messages + volatile poll
// (no mbarrier). Argmax tie-breaks via ballot+ffs (index-ordered layout).

#define FPS_B  8
#define FPS_N  65536
#define FPS_NP 1024
#define FPS_CL 8
#define FPS_T  1024
#define NW     (FPS_T / 32)
#define NF4    2              // float4 loads per plane per thread
#define NPAIR  4              // f32x2 pairs per thread (8 points)

__device__ __forceinline__ uint64_t pack2(float a, float b) {
    uint64_t r; asm("mov.b64 %0, {%1, %2};" : "=l"(r) : "f"(a), "f"(b)); return r;
}
__device__ __forceinline__ void unpack2(uint64_t v, float& a, float& b) {
    asm("mov.b64 {%0, %1}, %2;" : "=f"(a), "=f"(b) : "l"(v));
}
__device__ __forceinline__ uint64_t add2(uint64_t a, uint64_t b) {
    uint64_t r; asm("add.rn.f32x2 %0, %1, %2;" : "=l"(r) : "l"(a), "l"(b)); return r;
}
__device__ __forceinline__ uint64_t mul2(uint64_t a, uint64_t b) {
    uint64_t r; asm("mul.rn.f32x2 %0, %1, %2;" : "=l"(r) : "l"(a), "l"(b)); return r;
}
__device__ __forceinline__ uint32_t ctarank() {
    uint32_t r; asm("mov.u32 %0, %%cluster_ctarank;" : "=r"(r)); return r;
}
__device__ __forceinline__ uint32_t smem_u32(const void* p) {
    uint32_t a;
    asm("{ .reg .u64 t; cvta.to.shared.u64 t, %1; cvt.u32.u64 %0, t; }" : "=r"(a) : "l"(p));
    return a;
}
__device__ __forceinline__ uint32_t redux_max_u32(uint32_t v) {
    uint32_t r; asm("redux.sync.max.u32 %0, %1, 0xFFFFFFFF;" : "=r"(r) : "r"(v)); return r;
}
__device__ __forceinline__ uint32_t mapa32(uint32_t laddr, uint32_t rank) {
    uint32_t r;
    asm("mapa.shared::cluster.u32 %0, %1, %2;" : "=r"(r) : "r"(laddr), "r"(rank));
    return r;
}
__device__ __forceinline__ void st_cluster_u64(uint32_t raddr, uint64_t v) {
    asm volatile("st.shared::cluster.u64 [%0], %1;" :: "r"(raddr), "l"(v) : "memory");
}
__device__ __forceinline__ void lds_volatile_v2(uint32_t addr, uint32_t& a, uint32_t& b) {
    asm volatile("ld.volatile.shared.v2.u32 {%0, %1}, [%2];"
                 : "=r"(a), "=r"(b) : "r"(addr) : "memory");
}

__global__ void __launch_bounds__(FPS_T, 1) __cluster_dims__(FPS_CL, 1, 1)
fps_kernel(const float* __restrict__ pts, float* __restrict__ out) {
    const int b      = blockIdx.x / FPS_CL;
    const uint32_t k = ctarank();
    const int tid    = threadIdx.x;
    const int lane   = tid & 31;
    const int wid    = tid >> 5;

    const float* __restrict__ xb = pts + (size_t)b * 3 * FPS_N;
    const float4* __restrict__ x4 = (const float4*)(xb);
    const float4* __restrict__ y4 = (const float4*)(xb + FPS_N);
    const float4* __restrict__ z4 = (const float4*)(xb + 2 * FPS_N);

    uint64_t xp[NPAIR], yp[NPAIR], zp[NPAIR];
    float dist[2 * NPAIR];
    int pbase[NF4];

    // CONSECUTIVE layout: thread t owns points [8t, 8t+8) of its CTA block.
    // => lane order == index order, warp order == index order, slot order == index order.
#pragma unroll
    for (int j = 0; j < NF4; j++) {
        int f = (int)k * (FPS_N / 4 / FPS_CL) + 2 * tid + j;
        pbase[j] = 4 * f;
        float4 vx = x4[f], vy = y4[f], vz = z4[f];
        xp[2*j+0] = pack2(vx.x, vx.y);  xp[2*j+1] = pack2(vx.z, vx.w);
        yp[2*j+0] = pack2(vy.x, vy.y);  yp[2*j+1] = pack2(vy.z, vy.w);
        zp[2*j+0] = pack2(vz.x, vz.y);  zp[2*j+1] = pack2(vz.z, vz.w);
    }
#pragma unroll
    for (int p = 0; p < 2 * NPAIR; p++) dist[p] = 1e10f;

    __shared__ uint64_t s_wkey[NW];                        // (d<<32)|idx per warp
    __shared__ alignas(16) unsigned long long s_key[2][FPS_CL]; // msg: lo=(tag<<24)|idx? see below
    __shared__ uint32_t s_hist[FPS_NP];

    // message u64 layout: [d:32][tag:8][idx:24]  (hi32=d, lo32=(tag<<24)|idx)
    const uint32_t pair0 = smem_u32(&s_key[0][0]);
    const uint32_t pair1 = smem_u32(&s_key[1][0]);

    uint32_t r_slot0 = 0, r_slot1 = 0;
    if (wid == 0 && lane < FPS_CL) {
        r_slot0 = mapa32(pair0 + 8u * k, (uint32_t)lane);
        r_slot1 = mapa32(pair1 + 8u * k, (uint32_t)lane);
    }

    if (tid < 2 * FPS_CL)                                  // init tags to 0xFF (never matches)
        ((unsigned long long*)s_key)[tid] = 0xFFFFFFFFFFFFFFFFull;
    if (tid == 0) s_hist[0] = 0;
    __syncthreads();
    asm volatile("barrier.cluster.arrive.aligned;" ::: "memory");
    asm volatile("barrier.cluster.wait.aligned;"   ::: "memory");

    float px = __ldg(&xb[0]);
    float py = __ldg(&xb[FPS_N]);
    float pz = __ldg(&xb[2 * FPS_N]);

    for (int it = 1; it < FPS_NP; it++) {
        const int u           = it - 1;
        const int buf         = u & 1;
        const uint32_t tag    = ((uint32_t)u >> 1) & 0xFFu;
        const uint32_t pbuf   = buf ? pair1 : pair0;
        const uint32_t r_slot = buf ? r_slot1 : r_slot0;

        uint64_t npx = pack2(-px, -px);
        uint64_t npy = pack2(-py, -py);
        uint64_t npz = pack2(-pz, -pz);

        // proven hot loop: packed distance + SEL-chain first-index argmax
        float bestd  = -1.0f;
        int   bestid = 0;
#pragma unroll
        for (int q = 0; q < NPAIR; q++) {
            uint64_t dx = add2(xp[q], npx);        // add(x,-p) bitwise == sub(x,p)
            uint64_t dy = add2(yp[q], npy);
            uint64_t dz = add2(zp[q], npz);
            // XLA order: (dx^2 + dy^2) + dz^2, separate .rn rounding
            uint64_t s = add2(add2(mul2(dx, dx), mul2(dy, dy)), mul2(dz, dz));
            float d0, d1; unpack2(s, d0, d1);
            const int p   = 2 * q;
            const int idx = pbase[q >> 1] + 2 * (q & 1);   // ascending within thread
            float n0 = fminf(dist[p], d0);     dist[p]     = n0;
            if (n0 > bestd) { bestd = n0; bestid = idx; }  // strict >: first idx wins
            float n1 = fminf(dist[p + 1], d1); dist[p + 1] = n1;
            if (n1 > bestd) { bestd = n1; bestid = idx + 1; }
        }

        // warp argmax: redux + ballot/ffs (lane order == index order)
        uint32_t db   = __float_as_uint(bestd);            // dists >= 0: u32 order == float
        uint32_t wmax = redux_max_u32(db);
        uint32_t msk  = __ballot_sync(0xFFFFFFFFu, db == wmax);
        if (lane == __ffs(msk) - 1)                        // lowest lane == smallest index
            s_wkey[wid] = ((uint64_t)wmax << 32) | (uint32_t)bestid;

        if (wid == 0) {
            asm volatile("bar.sync 1, %0;" :: "r"(FPS_T) : "memory");
            uint64_t wkey = s_wkey[lane];                  // NW == 32; warp order == index order
            uint32_t d  = (uint32_t)(wkey >> 32);
            uint32_t wi = (uint32_t)wkey;
            uint32_t m    = redux_max_u32(d);
            uint32_t m2   = __ballot_sync(0xFFFFFFFFu, d == m);
            int ws        = __ffs(m2) - 1;                 // lowest warp == smallest index
            uint32_t widx0 = __shfl_sync(0xFFFFFFFFu, wi, ws);
            if (lane < FPS_CL) {
                uint64_t msg = ((uint64_t)m << 32) | (tag << 24) | widx0;
                st_cluster_u64(r_slot, msg);
            }
        } else {
            asm volatile("bar.arrive 1, %0;" :: "r"(FPS_T) : "memory");
        }

        // poll own slots until all CL tags match this phase
        uint32_t d = 0, ti = 0;
        for (;;) {
            if (lane < FPS_CL) lds_volatile_v2(pbuf + 8u * (uint32_t)lane, ti, d);
            // note v2 {lo,hi}: lo = (tag<<24)|idx, hi = d
            if (__all_sync(0xFFFFFFFFu, (lane >= FPS_CL) || ((ti >> 24) == tag))) break;
        }

        // cluster argmax over 8 slots: redux + ballot/ffs (slot order == index order)
        uint32_t dm  = redux_max_u32(d);                   // lanes>=CL hold d=0 (can't win wrongly)
        uint32_t m3  = __ballot_sync(0xFFFFFFFFu, (lane < FPS_CL) && (d == dm));
        int rs       = __ffs(m3) - 1;
        uint32_t tw  = __shfl_sync(0xFFFFFFFFu, ti, rs);
        const int widx = (int)(tw & 0x00FFFFFFu);

        px = __ldcg(&xb[widx]);
        py = __ldcg(&xb[FPS_N + widx]);
        pz = __ldcg(&xb[2 * FPS_N + widx]);

        if (tid == 0) s_hist[it] = (uint32_t)widx;
    }

    // final gather: rank-0 CTA writes (3, 1024) for its batch
    __syncthreads();
    if (k == 0) {
        for (int i = tid; i < 3 * FPS_NP; i += FPS_T) {
            int ip = i & (FPS_NP - 1);
            int c  = i >> 10;
            uint32_t idx = s_hist[ip];
            out[((size_t)b * 3 + c) * FPS_NP + ip] = xb[(size_t)c * FPS_N + idx];
        }
    }
}

extern "C" void kernel_launch(void* const* d_in, const int* in_sizes, int n_in,
                              void* d_out, int out_size) {
    const float* pts = (const float*)d_in[0];
    float* out = (float*)d_out;
    fps_kernel<<<FPS_B * FPS_CL, FPS_T>>>(pts, out);
}